// round 13
// baseline (speedup 1.0000x reference)
#include <cuda_runtime.h>

#define XSIZE 256

// Pinned sincos: volatile asm is NOT reordered by ptxas, so the source-level
// interleaving of patch-B MUFU ops with patch-A FMA ops survives into SASS.
#define SINCOSV(P, S, C)                                              \
    asm volatile("sin.approx.f32 %0, %2;\n\t"                         \
                 "cos.approx.f32 %1, %2;"                             \
                 : "=f"(S), "=f"(C) : "f"(P));

// phase prep: h_e = y3 ± y2 ± y1 ± y0 on halved inputs (h = t/2)
#define PREP(H, Y0, Y1, Y2, Y3)                                       \
    {                                                                 \
        const float ap = (Y3) + (Y2), am = (Y3) - (Y2);               \
        const float bp = (Y1) + (Y0), bm = (Y1) - (Y0);               \
        H[0] = am - bp; H[1] = am - bm; H[2] = am + bm; H[3] = am + bp; \
        H[4] = ap - bp; H[5] = ap - bm; H[6] = ap + bm; H[7] = ap + bp; \
    }

// diag pair (8|e, e^7): phi = -h^2 ∓ h (global phase dropped)
#define EMIT(VR, VI, H, E)                                            \
    {                                                                 \
        const float he = H[E];                                        \
        const float p1 = __fmaf_rn(he, -he, -he);                     \
        const float p0 = __fmaf_rn(he, -he,  he);                     \
        SINCOSV(p1, VI[8 | (E)], VR[8 | (E)])                         \
        SINCOSV(p0, VI[(E) ^ 7], VR[(E) ^ 7])                         \
    }

// one tangent-form RX butterfly (4 FFMA)
#define BF(VR, VI, Q, M, TQ)                                          \
    {                                                                 \
        const int j0 = (((M) >> (Q)) << ((Q) + 1)) | ((M) & ((1 << (Q)) - 1)); \
        const int j1 = j0 | (1 << (Q));                               \
        const float ar = VR[j0], ai = VI[j0];                         \
        const float br = VR[j1], bim = VI[j1];                        \
        VR[j0] = __fmaf_rn( (TQ), bim, ar);                           \
        VI[j0] = __fmaf_rn(-(TQ), br,  ai);                           \
        VR[j1] = __fmaf_rn( (TQ), ai,  br);                           \
        VI[j1] = __fmaf_rn(-(TQ), ar,  bim);                          \
    }

#define LH(VR, VI, Q, MB, TQ)                                         \
    BF(VR, VI, Q, (MB) + 0, TQ) BF(VR, VI, Q, (MB) + 1, TQ)           \
    BF(VR, VI, Q, (MB) + 2, TQ) BF(VR, VI, Q, (MB) + 3, TQ)

// CNOT ring + per-qubit Z readout = parity-masked probability sums
#define READOUT(VR, VI, O, SC)                                        \
    {                                                                 \
        float o0 = 0.f, o1 = 0.f, o2 = 0.f, o3 = 0.f;                 \
        _Pragma("unroll")                                             \
        for (int k = 0; k < 16; k++) {                                \
            const float p = __fmaf_rn(VR[k], VR[k], VI[k] * VI[k]);   \
            if (__popc(k & 0xF) & 1) o0 += p;                         \
            if (__popc(k & 0x7) & 1) o1 += p;                         \
            if (__popc(k & 0x3) & 1) o2 += p;                         \
            if (__popc(k & 0xE) & 1) o3 += p;                         \
        }                                                             \
        O.x = (SC) * o0; O.y = (SC) * o1;                             \
        O.z = (SC) * o2; O.w = (SC) * o3;                             \
    }

// 64 threads/block; each thread pipelines TWO patches. Patch-B sincos (MUFU)
// is pinned between patch-A butterfly chunks (FMA) so both ports run at once.
__global__ __launch_bounds__(64) void qconv_kernel10(const float* __restrict__ x,
                                                     const float* __restrict__ w,
                                                     float* __restrict__ out)
{
    __shared__ float sh[5];
    if (threadIdx.x == 0) {
        float C = 1.0f;
#pragma unroll
        for (int q = 0; q < 4; q++) {
            float cq, sq;
            __sincosf(0.5f * __ldg(w + q), &sq, &cq);
            sh[q] = __fdividef(sq, cq);     // tan(w_q/2)
            C *= cq;
        }
        sh[4] = 0.0625f * C * C;
    }
    __syncthreads();
    const float u0 = sh[0], u1 = sh[1], u2 = sh[2], u3 = sh[3];
    const float scale = sh[4];

    const int t  = threadIdx.x;
    const int bi = blockIdx.x;              // b*128 + i
    const int i  = bi & 127;
    const size_t base = ((size_t)(bi >> 7) * XSIZE + 2 * i) * XSIZE + 4 * t;
    const float4 r0 = *reinterpret_cast<const float4*>(x + base);
    const float4 r1 = *reinterpret_cast<const float4*>(x + base + XSIZE);

    float hA[8], hB[8];
    PREP(hA, 0.5f * r0.x, 0.5f * r0.y, 0.5f * r1.x, 0.5f * r1.y);
    PREP(hB, 0.5f * r0.z, 0.5f * r0.w, 0.5f * r1.z, 0.5f * r1.w);

    float vrA[16], viA[16], vrB[16], viB[16];

    // window 1: A phases (MUFU; fills the MUFU queue)
    EMIT(vrA, viA, hA, 0) EMIT(vrA, viA, hA, 1)
    EMIT(vrA, viA, hA, 2) EMIT(vrA, viA, hA, 3)
    EMIT(vrA, viA, hA, 4) EMIT(vrA, viA, hA, 5)
    EMIT(vrA, viA, hA, 6) EMIT(vrA, viA, hA, 7)

    // window 2: B phases (MUFU, pinned) interleaved with A butterflies (FMA)
    EMIT(vrB, viB, hB, 0) LH(vrA, viA, 0, 0, u0)
    EMIT(vrB, viB, hB, 1) LH(vrA, viA, 0, 4, u0)
    EMIT(vrB, viB, hB, 2) LH(vrA, viA, 1, 0, u1)
    EMIT(vrB, viB, hB, 3) LH(vrA, viA, 1, 4, u1)
    EMIT(vrB, viB, hB, 4) LH(vrA, viA, 2, 0, u2)
    EMIT(vrB, viB, hB, 5) LH(vrA, viA, 2, 4, u2)
    EMIT(vrB, viB, hB, 6) LH(vrA, viA, 3, 0, u3)
    EMIT(vrB, viB, hB, 7) LH(vrA, viA, 3, 4, u3)

    // window 3: A readout + all of B's FMA work
    float4 oa, ob;
    READOUT(vrA, viA, oa, scale)

    LH(vrB, viB, 0, 0, u0) LH(vrB, viB, 0, 4, u0)
    LH(vrB, viB, 1, 0, u1) LH(vrB, viB, 1, 4, u1)
    LH(vrB, viB, 2, 0, u2) LH(vrB, viB, 2, 4, u2)
    LH(vrB, viB, 3, 0, u3) LH(vrB, viB, 3, 4, u3)
    READOUT(vrB, viB, ob, scale)

    float* dst = out + (size_t)bi * 512 + 8 * t;
    reinterpret_cast<float4*>(dst)[0] = oa;
    reinterpret_cast<float4*>(dst)[1] = ob;
}

extern "C" void kernel_launch(void* const* d_in, const int* in_sizes, int n_in,
                              void* d_out, int out_size)
{
    const float* x = (const float*)d_in[0];
    const float* w = (const float*)d_in[1];
    float* out = (float*)d_out;
    const int batch = in_sizes[0] / (XSIZE * XSIZE);
    qconv_kernel10<<<batch * 128, 64>>>(x, w, out);
}